// round 5
// baseline (speedup 1.0000x reference)
#include <cuda_runtime.h>
#include <cuda_fp16.h>
#include <cstdint>

#define DIM 128

// Capacity limits (problem spec: N = 110000 joint rows, E = 1200000 per matrix).
#define NMAX 131072          // max N
#define EMAX 1310720         // max edges per matrix

// Static scratch (no allocations allowed).
__device__ int   g_cnt[2 * NMAX];         // per-(matrix,row) edge counts
__device__ int   g_ofs[2 * NMAX];         // CSR row start (non-monotonic, valid partition)
__device__ int   g_cur[2 * NMAX];         // scatter cursors
__device__ int   g_counter;               // scan block-offset counter
__device__ int2  g_edge[2 * EMAX + 8];    // CSR edges: (col, val_bits_fp32) + pad
__device__ uint2 g_x1h[NMAX * (DIM / 4)]; // fp16 copy of x1: 32 uint2 per row

// ---------------------------------------------------------------------------
// K1 (fused): build x1 fp32 into out[0], build fp16 copy g_x1h,
//             histogram edge rows (4 edges per thread, int4 loads).
// ---------------------------------------------------------------------------
__global__ void k_init_hist(const float4* __restrict__ node4,
                            const float4* __restrict__ attri4,
                            float4* __restrict__ out4,
                            const int* __restrict__ r1,
                            const int* __restrict__ r2,
                            long node_f4, long total_f4,
                            int E, int n)
{
    long i = (long)blockIdx.x * blockDim.x + threadIdx.x;

    if (i < total_f4) {
        float4 f = (i < node_f4) ? node4[i] : attri4[i - node_f4];
        out4[i] = f;                                   // fp32 x1 (exact output)
        __half2 h01 = __floats2half2_rn(f.x, f.y);
        __half2 h23 = __floats2half2_rn(f.z, f.w);
        uint2 u;
        u.x = *reinterpret_cast<unsigned*>(&h01);
        u.y = *reinterpret_cast<unsigned*>(&h23);
        g_x1h[i] = u;                                  // fp16 x1 (gather copy)
    }

    // Histogram: thread j handles 4 edges of one matrix.
    int E4 = E >> 2;                                   // E % 4 == 0 fast path
    if (i < 2L * E4 && (E & 3) == 0) {
        int m = (i < E4) ? 0 : 1;
        long e4 = (m == 0) ? i : (i - E4);
        const int4* rp = reinterpret_cast<const int4*>(m == 0 ? r1 : r2);
        int4 r = __ldg(rp + e4);
        int base = m * n;
        atomicAdd(g_cnt + base + r.x, 1);
        atomicAdd(g_cnt + base + r.y, 1);
        atomicAdd(g_cnt + base + r.z, 1);
        atomicAdd(g_cnt + base + r.w, 1);
    } else if ((E & 3) != 0) {
        // generic fallback (one edge per thread over both matrices)
        long twoE = 2L * E;
        if (i < twoE) {
            int b = (i < E) ? __ldg(r1 + i) : (n + __ldg(r2 + (i - E)));
            atomicAdd(g_cnt + b, 1);
        }
    }
}

// ---------------------------------------------------------------------------
// K2: single-pass exclusive scan (warp shuffles + atomic block offset).
// ---------------------------------------------------------------------------
__global__ void k_scan(int n2)
{
    __shared__ int ws[32];
    __shared__ int base;
    int t = threadIdx.x, lane = t & 31, w = t >> 5;
    int i = blockIdx.x * 1024 + t;
    int v = (i < n2) ? g_cnt[i] : 0;

    int x = v;
#pragma unroll
    for (int d = 1; d < 32; d <<= 1) {
        int y = __shfl_up_sync(0xffffffffu, x, d);
        if (lane >= d) x += y;
    }
    if (lane == 31) ws[w] = x;
    __syncthreads();
    if (w == 0) {
        int s = ws[lane];
#pragma unroll
        for (int d = 1; d < 32; d <<= 1) {
            int y = __shfl_up_sync(0xffffffffu, s, d);
            if (lane >= d) s += y;
        }
        ws[lane] = s;
    }
    __syncthreads();
    if (t == 0) base = atomicAdd(&g_counter, ws[31]);
    int incl = x + (w > 0 ? ws[w - 1] : 0);
    __syncthreads();
    if (i < n2) {
        int excl = base + incl - v;
        g_ofs[i] = excl;
        g_cur[i] = excl;
    }
}

// ---------------------------------------------------------------------------
// K3: permute edges into CSR order, 4 edges per thread (vector loads).
// ---------------------------------------------------------------------------
__global__ void k_permute(const int* __restrict__ r1, const int* __restrict__ c1,
                          const float* __restrict__ v1,
                          const int* __restrict__ r2, const int* __restrict__ c2,
                          const float* __restrict__ v2,
                          int E, int n)
{
    long i = (long)blockIdx.x * blockDim.x + threadIdx.x;
    int E4 = E >> 2;

    if ((E & 3) == 0) {
        if (i >= 2L * E4) return;
        int m = (i < E4) ? 0 : 1;
        long e4 = (m == 0) ? i : (i - E4);
        const int4*   rp = reinterpret_cast<const int4*>(m == 0 ? r1 : r2);
        const int4*   cp = reinterpret_cast<const int4*>(m == 0 ? c1 : c2);
        const float4* vp = reinterpret_cast<const float4*>(m == 0 ? v1 : v2);
        int4   r = __ldg(rp + e4);
        int4   c = __ldg(cp + e4);
        float4 v = __ldg(vp + e4);
        int base = m * n;
        int p0 = atomicAdd(g_cur + base + r.x, 1);
        int p1 = atomicAdd(g_cur + base + r.y, 1);
        int p2 = atomicAdd(g_cur + base + r.z, 1);
        int p3 = atomicAdd(g_cur + base + r.w, 1);
        g_edge[p0] = make_int2(c.x, __float_as_int(v.x));
        g_edge[p1] = make_int2(c.y, __float_as_int(v.y));
        g_edge[p2] = make_int2(c.z, __float_as_int(v.z));
        g_edge[p3] = make_int2(c.w, __float_as_int(v.w));
    } else {
        long tot = 2L * E;
        if (i >= tot) return;
        int b, col; float val;
        if (i < E) { b = __ldg(r1 + i);     col = __ldg(c1 + i);     val = __ldg(v1 + i); }
        else       { long e = i - E;
                     b = n + __ldg(r2 + e); col = __ldg(c2 + e);     val = __ldg(v2 + e); }
        int pos = atomicAdd(g_cur + b, 1);
        g_edge[pos] = make_int2(col, __float_as_int(val));
    }
}

// ---------------------------------------------------------------------------
// K4: gather SpMM. ONE WARP PER ROW; lane owns 4 of 128 floats (uint2 fp16).
// Edge meta fetched by broadcast LDG (all lanes same addr, no shuffles).
// 4 edges per iteration, tail handled by index-clamp + zeroed val (no branch).
// ---------------------------------------------------------------------------
__global__ void __launch_bounds__(256)
k_gather(float* __restrict__ out, int n, long total_f)
{
    int gw   = (int)(((long)blockIdx.x * blockDim.x + threadIdx.x) >> 5);
    int lane = threadIdx.x & 31;
    int n2 = 2 * n;
    if (gw >= n2) return;

    int start = __ldg(g_ofs + gw);
    int cnt   = __ldg(g_cnt + gw);

    float a0 = 0.f, a1 = 0.f, a2 = 0.f, a3 = 0.f;
    const int2* ep = (const int2*)g_edge + start;

    for (int k = 0; k < cnt; k += 4) {
        int   c[4];
        float v[4];
        uint2 x[4];
#pragma unroll
        for (int j = 0; j < 4; j++) {
            int kk  = k + j;
            int idx = kk < cnt ? kk : cnt - 1;      // clamp (reread last edge)
            int2 e  = __ldg(ep + idx);              // broadcast load
            c[j] = e.x;
            v[j] = (kk < cnt) ? __int_as_float(e.y) : 0.f;
        }
#pragma unroll
        for (int j = 0; j < 4; j++)
            x[j] = __ldg(g_x1h + (long)c[j] * 32 + lane);
#pragma unroll
        for (int j = 0; j < 4; j++) {
            float2 f01 = __half22float2(*reinterpret_cast<__half2*>(&x[j].x));
            float2 f23 = __half22float2(*reinterpret_cast<__half2*>(&x[j].y));
            a0 = fmaf(v[j], f01.x, a0);
            a1 = fmaf(v[j], f01.y, a1);
            a2 = fmaf(v[j], f23.x, a2);
            a3 = fmaf(v[j], f23.y, a3);
        }
    }

    long row_off = (gw < n) ? (total_f + (long)gw * DIM)
                            : (2 * total_f + (long)(gw - n) * DIM);
    reinterpret_cast<float4*>(out + row_off)[lane] = make_float4(a0, a1, a2, a3);
}

// ---------------------------------------------------------------------------
extern "C" void kernel_launch(void* const* d_in, const int* in_sizes, int n_in,
                              void* d_out, int out_size)
{
    const float* node  = (const float*)d_in[0];
    const float* attri = (const float*)d_in[1];
    const int*   r1    = (const int*)  d_in[2];
    const int*   c1    = (const int*)  d_in[3];
    const float* v1    = (const float*)d_in[4];
    const int*   r2    = (const int*)  d_in[5];
    const int*   c2    = (const int*)  d_in[6];
    const float* v2    = (const float*)d_in[7];
    float* out = (float*)d_out;

    long node_f  = in_sizes[0];
    long attri_f = in_sizes[1];
    long total_f = node_f + attri_f;
    int  E       = in_sizes[2];
    int  n       = (int)(total_f / DIM);
    int  n2      = 2 * n;

    // K0: zero counters (memset nodes are graph-capturable).
    void *p_cnt = nullptr, *p_counter = nullptr;
    cudaGetSymbolAddress(&p_cnt, g_cnt);
    cudaGetSymbolAddress(&p_counter, g_counter);
    cudaMemsetAsync(p_cnt, 0, (size_t)n2 * sizeof(int));
    cudaMemsetAsync(p_counter, 0, sizeof(int));

    // K1: fused copy + fp16 convert + histogram
    {
        long total4 = total_f / 4;
        long histN  = ((E & 3) == 0) ? (2L * (E >> 2)) : (2L * E);
        long end = total4 > histN ? total4 : histN;
        int  threads = 256;
        long blocks = (end + threads - 1) / threads;
        k_init_hist<<<(unsigned)blocks, threads>>>(
            (const float4*)node, (const float4*)attri, (float4*)out,
            r1, r2, node_f / 4, total4, E, n);
    }

    // K2: scan
    k_scan<<<(n2 + 1023) / 1024, 1024>>>(n2);

    // K3: permute (4 edges/thread)
    {
        long workers = ((E & 3) == 0) ? (2L * (E >> 2)) : (2L * E);
        int  threads = 256;
        long blocks = (workers + threads - 1) / threads;
        k_permute<<<(unsigned)blocks, threads>>>(r1, c1, v1, r2, c2, v2, E, n);
    }

    // K4: gather SpMM (one warp per row)
    {
        int threads = 256;
        long blocks = ((long)n2 * 32 + threads - 1) / threads;
        k_gather<<<(unsigned)blocks, threads>>>(out, n, total_f);
    }
}